// round 11
// baseline (speedup 1.0000x reference)
#include <cuda_runtime.h>
#include <cuda_bf16.h>
#include <math.h>
#include <stdint.h>

// ============================================================================
// HypHawkes, int8 IMMA path (legacy mma.sync m16n8k32 s8 — historically 2x
// the fp16 mma.sync rate; fp8 QMMA measured 1x, tcgen05 compile-blocked).
//
//   K1/K2: row-scale query/context (fused expmap0+project) -> s8 x512
//   K3:    W -> s8 x512
//   K4:    GEMM1 q2 = qs @ wb^T   (s8 IMMA, s32 acc EXACT, s8 out /512)
//   K5:    GEMM2 scores = q2 @ cs^T (s8 IMMA, s32 acc, bf16 out)
//   K6:    row softmax(scores/(d*512^2)) + expmap0/project -> out (fp32)
//
// GEMM: CTA 128x128x128B, 3-stage cp.async (96 KB -> 2 CTAs/SM), 8 warps
// (2m x 4n), warp tile 64x32, ldmatrix.x4 fragments (s8-k32 fragments are
// layout-identical to e4m3-k32 == bf16-k16 in b16 view), XOR-swizzled smem.
// Skeleton identical to the round-9 fp8 kernel that passed correctness.
// ============================================================================

#define MAXN 4096
#define MAXD 1024

__device__ int8_t        g_qs[MAXN * MAXD];
__device__ int8_t        g_cs[MAXN * MAXD];
__device__ int8_t        g_wb[MAXD * MAXD];
__device__ int8_t        g_q2[MAXN * MAXD];
__device__ __nv_bfloat16 g_scores[(size_t)MAXN * MAXN];

#define MIN_NORM 1e-5f
#define PROJ_EPS 4e-3f
#define QS       512.0f          // quantization scale
#define INV_QS   (1.0f / 512.0f)

// ---------------------------------------------------------------------------
// helpers
// ---------------------------------------------------------------------------
__device__ __forceinline__ uint32_t smem_u32(const void* p) {
    uint32_t a;
    asm("{ .reg .u64 t; cvta.to.shared.u64 t, %1; cvt.u32.u64 %0, t; }"
        : "=r"(a) : "l"(p));
    return a;
}
__device__ __forceinline__ void cp16(uint32_t dst, const void* src) {
    asm volatile("cp.async.cg.shared.global [%0], [%1], 16;" :: "r"(dst), "l"(src));
}
#define CP_COMMIT() asm volatile("cp.async.commit_group;" ::: "memory")
#define CP_WAIT(N)  asm volatile("cp.async.wait_group %0;" :: "n"(N) : "memory")

__device__ __forceinline__ void ldsm_x4(uint32_t* r, uint32_t addr) {
    asm volatile("ldmatrix.sync.aligned.m8n8.x4.shared.b16 {%0,%1,%2,%3}, [%4];"
                 : "=r"(r[0]), "=r"(r[1]), "=r"(r[2]), "=r"(r[3]) : "r"(addr));
}
// int8 IMMA: D[16x8] += A[16x32] * B[32x8], s32 accumulate (exact)
__device__ __forceinline__ void imma16832(int* c, const uint32_t* a, const uint32_t* b) {
    asm volatile(
        "mma.sync.aligned.m16n8k32.row.col.s32.s8.s8.s32 "
        "{%0,%1,%2,%3}, {%4,%5,%6,%7}, {%8,%9}, {%0,%1,%2,%3};\n"
        : "+r"(c[0]), "+r"(c[1]), "+r"(c[2]), "+r"(c[3])
        : "r"(a[0]), "r"(a[1]), "r"(a[2]), "r"(a[3]), "r"(b[0]), "r"(b[1]));
}
__device__ __forceinline__ int q_s8(float x) {
    int v = __float2int_rn(x);
    return max(-127, min(127, v));
}

// ---------------------------------------------------------------------------
// K1/K2: per-row hyperbolic scale + quantize to s8 (x QS)
// scale = min(tanh(sqrt_c*r), 1-eps)/(sqrt_c*r), r = max(||u||, 1e-5)
// ---------------------------------------------------------------------------
__global__ __launch_bounds__(256)
void scale_rows_s8_kernel(const float* __restrict__ in, int8_t* __restrict__ out,
                          const float* __restrict__ c, int d) {
    __shared__ float sh[8];
    const int row = blockIdx.x;
    const int tid = threadIdx.x;
    const float4* r = (const float4*)(in + (size_t)row * d);
    const int d4 = d >> 2;
    float ss = 0.f;
    for (int i = tid; i < d4; i += 256) {
        float4 v = r[i];
        ss = fmaf(v.x, v.x, fmaf(v.y, v.y, fmaf(v.z, v.z, fmaf(v.w, v.w, ss))));
    }
#pragma unroll
    for (int o = 16; o; o >>= 1) ss += __shfl_xor_sync(0xffffffffu, ss, o);
    if ((tid & 31) == 0) sh[tid >> 5] = ss;
    __syncthreads();
    const float tot = sh[0] + sh[1] + sh[2] + sh[3] + sh[4] + sh[5] + sh[6] + sh[7];
    const float sc = sqrtf(c[0]);
    const float rn = fmaxf(sqrtf(tot), MIN_NORM);
    const float t  = fminf(tanhf(sc * rn), 1.0f - PROJ_EPS);
    const float scale = (t / (sc * rn)) * QS;
    uint32_t* o = (uint32_t*)(out + (size_t)row * d);
    for (int i = tid; i < d4; i += 256) {
        float4 v = r[i];
        int a = q_s8(v.x * scale), b = q_s8(v.y * scale);
        int e = q_s8(v.z * scale), f = q_s8(v.w * scale);
        o[i] = (uint32_t)(a & 0xFF) | ((uint32_t)(b & 0xFF) << 8) |
               ((uint32_t)(e & 0xFF) << 16) | ((uint32_t)(f & 0xFF) << 24);
    }
}

// ---------------------------------------------------------------------------
// K3: fp32 -> s8 quantize (x QS)
// ---------------------------------------------------------------------------
__global__ __launch_bounds__(256)
void convert_w_s8_kernel(const float4* __restrict__ in, uint32_t* __restrict__ out,
                         int n4) {
    int i = blockIdx.x * blockDim.x + threadIdx.x;
    if (i < n4) {
        float4 v = in[i];
        int a = q_s8(v.x * QS), b = q_s8(v.y * QS);
        int e = q_s8(v.z * QS), f = q_s8(v.w * QS);
        out[i] = (uint32_t)(a & 0xFF) | ((uint32_t)(b & 0xFF) << 8) |
                 ((uint32_t)(e & 0xFF) << 16) | ((uint32_t)(f & 0xFF) << 24);
    }
}

// ---------------------------------------------------------------------------
// s8 GEMM (TN): C[M,N] = A[M,K] @ B[N,K]^T, s8 in, s32 acc.
// CTA 128x128, K-tile 128 bytes, 3 stages, 96 KB smem, 2 CTAs/SM.
// OUT_S8: C = round(acc/512) clamped s8; else C = (float)acc as bf16.
// ---------------------------------------------------------------------------
#define BM 128
#define BN 128
#define BKB 128                       // K bytes (=elements) per tile
#define STG 3
#define A_ST (BM * BKB)               // 16384 B
#define B_ST (BN * BKB)               // 16384 B
#define B_BASE (STG * A_ST)           // 49152
#define GSMEM (B_BASE + STG * B_ST)   // 98304 = 96 KB

extern __shared__ __align__(1024) char dyn_smem[];

template <bool OUT_S8>
__global__ __launch_bounds__(256, 2)
void gemm_s8_kernel(const int8_t* __restrict__ A,
                    const int8_t* __restrict__ B,
                    void* __restrict__ Cv, int M, int N, int K) {
    const uint32_t sb = smem_u32(dyn_smem);
    const int tid  = threadIdx.x;
    const int wid  = tid >> 5;
    const int lane = tid & 31;
    const int bm = blockIdx.y * BM;
    const int bn = blockIdx.x * BN;
    const int wm = (wid & 1) * 64;    // 2 warps in m
    const int wn = (wid >> 1) * 32;   // 4 warps in n
    const int NK = K / BKB;

    int acc[4][4][4];
#pragma unroll
    for (int i = 0; i < 4; i++)
#pragma unroll
        for (int j = 0; j < 4; j++)
#pragma unroll
            for (int k = 0; k < 4; k++) acc[i][j][k] = 0;

    // cp.async staging: rows 128 B = 8 x 16B chunks; swizzle chunk ^= (row&7)
    auto load_stage = [&](int j) {
        const int s = (j % STG);
        const uint32_t ab = sb + s * A_ST;
        const uint32_t bb = sb + B_BASE + s * B_ST;
        const int8_t* Aj = A + (size_t)bm * K + (size_t)j * BKB;
        const int8_t* Bj = B + (size_t)bn * K + (size_t)j * BKB;
#pragma unroll
        for (int i = 0; i < 4; ++i) {
            int cid = tid + 256 * i;
            int row = cid >> 3, seg = cid & 7;
            uint32_t off = (uint32_t)(row * 128) + (uint32_t)((seg ^ (row & 7)) * 16);
            cp16(ab + off, Aj + (size_t)row * K + seg * 16);
        }
#pragma unroll
        for (int i = 0; i < 4; ++i) {
            int cid = tid + 256 * i;
            int row = cid >> 3, seg = cid & 7;
            uint32_t off = (uint32_t)(row * 128) + (uint32_t)((seg ^ (row & 7)) * 16);
            cp16(bb + off, Bj + (size_t)row * K + seg * 16);
        }
    };

#pragma unroll
    for (int j = 0; j < STG - 1; ++j) { load_stage(j); CP_COMMIT(); }

    // LDSM addressing (b16-element view; s8 k32 frag == bf16 k16 frag)
    const int sub  = lane >> 3;   // 0..3
    const int trow = lane & 7;
    const int a_row_l = wm + (sub & 1) * 8 + trow;   // + mi*16
    const int a_kkB   = (sub >> 1) * 16;             // byte col within k-step
    const int b_row_l = wn + (sub >> 1) * 8 + trow;  // + pi*16
    const int b_kkB   = (sub & 1) * 16;
    const uint32_t sw = (uint32_t)trow << 4;         // XOR swizzle bytes [6:4]

    for (int kt = 0; kt < NK; ++kt) {
        CP_WAIT(1);
        __syncthreads();
        const int jn = kt + STG - 1;
        if (jn < NK) load_stage(jn);
        CP_COMMIT();

        const int s = kt % STG;
        const uint32_t abase = sb + s * A_ST;
        const uint32_t bbase = sb + B_BASE + s * B_ST;

#pragma unroll
        for (int ks = 0; ks < 4; ++ks) {           // 4 x k32 per 128B tile
            const int k0 = ks * 32;                // byte offset
            uint32_t af[4][4], bf[2][4];
#pragma unroll
            for (int mi = 0; mi < 4; ++mi) {
                uint32_t col = (uint32_t)(k0 + a_kkB) ^ sw;
                ldsm_x4(af[mi], abase + (uint32_t)((a_row_l + mi * 16) * 128) + col);
            }
#pragma unroll
            for (int pi = 0; pi < 2; ++pi) {
                uint32_t col = (uint32_t)(k0 + b_kkB) ^ sw;
                ldsm_x4(bf[pi], bbase + (uint32_t)((b_row_l + pi * 16) * 128) + col);
            }
#pragma unroll
            for (int mi = 0; mi < 4; ++mi)
#pragma unroll
                for (int ni = 0; ni < 4; ++ni)
                    imma16832(acc[mi][ni], af[mi], &bf[ni >> 1][(ni & 1) * 2]);
        }
    }

    // epilogue: thread holds (row,col..col+1) = c0,c1 and (row+8,...) = c2,c3
    const int g  = lane >> 2;
    const int tg = lane & 3;
    if (OUT_S8) {
        int8_t* C = (int8_t*)Cv;
#pragma unroll
        for (int mi = 0; mi < 4; ++mi) {
            const int row = bm + wm + mi * 16 + g;
#pragma unroll
            for (int ni = 0; ni < 4; ++ni) {
                const int col = bn + wn + ni * 8 + tg * 2;
                int r0 = q_s8((float)acc[mi][ni][0] * INV_QS);
                int r1 = q_s8((float)acc[mi][ni][1] * INV_QS);
                int r2 = q_s8((float)acc[mi][ni][2] * INV_QS);
                int r3 = q_s8((float)acc[mi][ni][3] * INV_QS);
                *(uint16_t*)&C[(size_t)row * N + col] =
                    (uint16_t)((r0 & 0xFF) | ((r1 & 0xFF) << 8));
                *(uint16_t*)&C[(size_t)(row + 8) * N + col] =
                    (uint16_t)((r2 & 0xFF) | ((r3 & 0xFF) << 8));
            }
        }
    } else {
        __nv_bfloat16* C = (__nv_bfloat16*)Cv;
#pragma unroll
        for (int mi = 0; mi < 4; ++mi) {
            const int row = bm + wm + mi * 16 + g;
#pragma unroll
            for (int ni = 0; ni < 4; ++ni) {
                const int col = bn + wn + ni * 8 + tg * 2;
                *(__nv_bfloat162*)&C[(size_t)row * N + col] =
                    __floats2bfloat162_rn((float)acc[mi][ni][0], (float)acc[mi][ni][1]);
                *(__nv_bfloat162*)&C[(size_t)(row + 8) * N + col] =
                    __floats2bfloat162_rn((float)acc[mi][ni][2], (float)acc[mi][ni][3]);
            }
        }
    }
}

// ---------------------------------------------------------------------------
// K6: row softmax(scores * inv_d) fused with expmap0+project (bf16 scores).
// inv_d folds quantization: logits = raw/(d * QS^2).
// ---------------------------------------------------------------------------
__global__ __launch_bounds__(256)
void softmax_proj_kernel(const __nv_bfloat16* __restrict__ S, float* __restrict__ out,
                         const float* __restrict__ c, int m, float inv_d) {
    __shared__ float sh[16];
    const int row = blockIdx.x;
    const int tid = threadIdx.x;

    const uint4* sv = (const uint4*)(S + (size_t)row * m) + tid * 2;
    uint4 u0 = sv[0], u1 = sv[1];
    float v[16];
    {
        const uint32_t* w = (const uint32_t*)&u0;
#pragma unroll
        for (int i = 0; i < 4; ++i) {
            __nv_bfloat162 h = *(__nv_bfloat162*)&w[i];
            v[2 * i]     = __bfloat162float(h.x);
            v[2 * i + 1] = __bfloat162float(h.y);
        }
        const uint32_t* w2 = (const uint32_t*)&u1;
#pragma unroll
        for (int i = 0; i < 4; ++i) {
            __nv_bfloat162 h = *(__nv_bfloat162*)&w2[i];
            v[8 + 2 * i]     = __bfloat162float(h.x);
            v[8 + 2 * i + 1] = __bfloat162float(h.y);
        }
    }

    float vmax = v[0];
#pragma unroll
    for (int i = 1; i < 16; ++i) vmax = fmaxf(vmax, v[i]);
#pragma unroll
    for (int o = 16; o; o >>= 1) vmax = fmaxf(vmax, __shfl_xor_sync(0xffffffffu, vmax, o));
    if ((tid & 31) == 0) sh[tid >> 5] = vmax;
    __syncthreads();
    const float rmax = fmaxf(fmaxf(fmaxf(sh[0], sh[1]), fmaxf(sh[2], sh[3])),
                             fmaxf(fmaxf(sh[4], sh[5]), fmaxf(sh[6], sh[7])));
    __syncthreads();

    float es = 0.f, e2 = 0.f;
#pragma unroll
    for (int i = 0; i < 16; ++i) {
        float e = __expf((v[i] - rmax) * inv_d);
        v[i] = e;
        es += e;
        e2 = fmaf(e, e, e2);
    }
#pragma unroll
    for (int o = 16; o; o >>= 1) {
        es += __shfl_xor_sync(0xffffffffu, es, o);
        e2 += __shfl_xor_sync(0xffffffffu, e2, o);
    }
    if ((tid & 31) == 0) { sh[tid >> 5] = es; sh[8 + (tid >> 5)] = e2; }
    __syncthreads();
    const float tes = sh[0] + sh[1] + sh[2] + sh[3] + sh[4] + sh[5] + sh[6] + sh[7];
    const float te2 = sh[8] + sh[9] + sh[10] + sh[11] + sh[12] + sh[13] + sh[14] + sh[15];

    const float inv = 1.f / tes;
    const float rn  = fmaxf(sqrtf(te2) * inv, MIN_NORM);
    const float sc  = sqrtf(c[0]);
    const float t   = fminf(tanhf(sc * rn), 1.0f - PROJ_EPS);
    const float scale = (t / (sc * rn)) * inv;

    float4* o = (float4*)(out + (size_t)row * m) + tid * 4;
#pragma unroll
    for (int i = 0; i < 4; ++i)
        o[i] = make_float4(v[4 * i] * scale, v[4 * i + 1] * scale,
                           v[4 * i + 2] * scale, v[4 * i + 3] * scale);
}

// ---------------------------------------------------------------------------
// kernel_launch: inputs: query[n,d], context[m,d], W[d,d], c[1]
// ---------------------------------------------------------------------------
extern "C" void kernel_launch(void* const* d_in, const int* in_sizes, int n_in,
                              void* d_out, int out_size) {
    const float* query   = (const float*)d_in[0];
    const float* context = (const float*)d_in[1];
    const float* W       = (const float*)d_in[2];
    const float* c       = (const float*)d_in[3];

    const int d = (int)(sqrt((double)in_sizes[2]) + 0.5);
    const int n = in_sizes[0] / d;
    const int m = in_sizes[1] / d;

    int8_t *qs, *cs, *wb, *q2;
    __nv_bfloat16* sco;
    cudaGetSymbolAddress((void**)&qs,  g_qs);
    cudaGetSymbolAddress((void**)&cs,  g_cs);
    cudaGetSymbolAddress((void**)&wb,  g_wb);
    cudaGetSymbolAddress((void**)&q2,  g_q2);
    cudaGetSymbolAddress((void**)&sco, g_scores);

    cudaFuncSetAttribute(gemm_s8_kernel<true>,
                         cudaFuncAttributeMaxDynamicSharedMemorySize, GSMEM);
    cudaFuncSetAttribute(gemm_s8_kernel<false>,
                         cudaFuncAttributeMaxDynamicSharedMemorySize, GSMEM);

    // K1/K2: hyperbolic row scaling -> s8 (x512)
    scale_rows_s8_kernel<<<n, 256>>>(query, qs, c, d);
    scale_rows_s8_kernel<<<m, 256>>>(context, cs, c, d);

    // K3: W -> s8 (x512)
    const int n4 = (d * d) / 4;
    convert_w_s8_kernel<<<(n4 + 255) / 256, 256>>>((const float4*)W, (uint32_t*)wb, n4);

    // K4: q2 = qs @ wb^T  (s8 out, /512 -> q2 = actual*512)
    gemm_s8_kernel<true><<<dim3(d / BN, n / BM), 256, GSMEM>>>(qs, wb, (void*)q2, n, d, d);

    // K5: scores = q2 @ cs^T  (bf16 out, = actual*262144)
    gemm_s8_kernel<false><<<dim3(m / BN, n / BM), 256, GSMEM>>>(q2, cs, (void*)sco, n, m, d);

    // K6: softmax(scores/(d*QS^2)) + expmap0/project -> out (fp32)
    softmax_proj_kernel<<<n, 256>>>(sco, (float*)d_out, c, m,
                                    1.0f / ((float)d * QS * QS));
}

// round 12
// speedup vs baseline: 2.1747x; 2.1747x over previous
#include <cuda_runtime.h>
#include <cuda_bf16.h>
#include <cuda_fp16.h>
#include <math.h>
#include <stdint.h>

// ============================================================================
// HypHawkes (legacy-HMMA path). Round-8 skeleton (best: 160.3us) with ONE
// change: fp16 inputs + fp16 accumulation in mma.sync (probing whether the
// f16-acc HMMA variant runs at 2x the f32-acc rate on sm_103a; fragments and
// addressing identical in b16 view, accumulator registers halve).
//
//   K1/K2: row-scale query/context (fused expmap0+project scalar) -> f16
//   K3:    W -> f16
//   K4:    GEMM1 q2[n,d] = qs @ wb^T      (mma.sync f16/f16-acc, f16 out)
//   K5:    GEMM2 scores[n,m] = q2 @ cs^T  (mma.sync f16/f16-acc, bf16 out)
//   K6:    row softmax(scores/d) + expmap0/project -> out (fp32)
//
// GEMM: CTA 128x128x64, 3-stage cp.async (96 KB -> 2 CTAs/SM), 8 warps
// (2m x 4n), warp tile 64x32, ldmatrix.x4 fragments, XOR-swizzled smem.
// ============================================================================

#define MAXN 4096
#define MAXD 1024

__device__ __half        g_qs[MAXN * MAXD];
__device__ __half        g_cs[MAXN * MAXD];
__device__ __half        g_wb[MAXD * MAXD];
__device__ __half        g_q2[MAXN * MAXD];
__device__ __nv_bfloat16 g_scores[(size_t)MAXN * MAXN];

#define MIN_NORM 1e-5f
#define PROJ_EPS 4e-3f

// ---------------------------------------------------------------------------
// helpers
// ---------------------------------------------------------------------------
__device__ __forceinline__ uint32_t smem_u32(const void* p) {
    uint32_t a;
    asm("{ .reg .u64 t; cvta.to.shared.u64 t, %1; cvt.u32.u64 %0, t; }"
        : "=r"(a) : "l"(p));
    return a;
}
__device__ __forceinline__ void cp16(uint32_t dst, const void* src) {
    asm volatile("cp.async.cg.shared.global [%0], [%1], 16;" :: "r"(dst), "l"(src));
}
#define CP_COMMIT() asm volatile("cp.async.commit_group;" ::: "memory")
#define CP_WAIT(N)  asm volatile("cp.async.wait_group %0;" :: "n"(N) : "memory")

__device__ __forceinline__ void ldsm_x4(uint32_t* r, uint32_t addr) {
    asm volatile("ldmatrix.sync.aligned.m8n8.x4.shared.b16 {%0,%1,%2,%3}, [%4];"
                 : "=r"(r[0]), "=r"(r[1]), "=r"(r[2]), "=r"(r[3]) : "r"(addr));
}
// f16 HMMA with f16 accumulate: C(2 regs = 4 halves) += A(4) * B(2)
__device__ __forceinline__ void mma16816_f16(uint32_t* c, const uint32_t* a,
                                             const uint32_t* b) {
    asm volatile(
        "mma.sync.aligned.m16n8k16.row.col.f16.f16.f16.f16 "
        "{%0,%1}, {%2,%3,%4,%5}, {%6,%7}, {%0,%1};\n"
        : "+r"(c[0]), "+r"(c[1])
        : "r"(a[0]), "r"(a[1]), "r"(a[2]), "r"(a[3]), "r"(b[0]), "r"(b[1]));
}

// ---------------------------------------------------------------------------
// K1/K2: per-row hyperbolic scale + fp32->f16
// scale = min(tanh(sqrt_c*r), 1-eps)/(sqrt_c*r), r = max(||u||, 1e-5)
// ---------------------------------------------------------------------------
__global__ __launch_bounds__(256)
void scale_rows_kernel(const float* __restrict__ in, __half* __restrict__ out,
                       const float* __restrict__ c, int d) {
    __shared__ float sh[8];
    const int row = blockIdx.x;
    const int tid = threadIdx.x;
    const float4* r = (const float4*)(in + (size_t)row * d);
    const int d4 = d >> 2;
    float ss = 0.f;
    for (int i = tid; i < d4; i += 256) {
        float4 v = r[i];
        ss = fmaf(v.x, v.x, fmaf(v.y, v.y, fmaf(v.z, v.z, fmaf(v.w, v.w, ss))));
    }
#pragma unroll
    for (int o = 16; o; o >>= 1) ss += __shfl_xor_sync(0xffffffffu, ss, o);
    if ((tid & 31) == 0) sh[tid >> 5] = ss;
    __syncthreads();
    const float tot = sh[0] + sh[1] + sh[2] + sh[3] + sh[4] + sh[5] + sh[6] + sh[7];
    const float sc = sqrtf(c[0]);
    const float rn = fmaxf(sqrtf(tot), MIN_NORM);
    const float t  = fminf(tanhf(sc * rn), 1.0f - PROJ_EPS);
    const float scale = t / (sc * rn);
    __half2* o = (__half2*)(out + (size_t)row * d);
    for (int i = tid; i < d4; i += 256) {
        float4 v = r[i];
        o[2 * i]     = __floats2half2_rn(v.x * scale, v.y * scale);
        o[2 * i + 1] = __floats2half2_rn(v.z * scale, v.w * scale);
    }
}

// ---------------------------------------------------------------------------
// K3: fp32 -> f16 convert
// ---------------------------------------------------------------------------
__global__ __launch_bounds__(256)
void convert_w_kernel(const float4* __restrict__ in, __half2* __restrict__ out,
                      int n4) {
    int i = blockIdx.x * blockDim.x + threadIdx.x;
    if (i < n4) {
        float4 v = in[i];
        out[2 * i]     = __floats2half2_rn(v.x, v.y);
        out[2 * i + 1] = __floats2half2_rn(v.z, v.w);
    }
}

// ---------------------------------------------------------------------------
// GEMM (TN): C[M,N] = A[M,K] @ B[N,K]^T, f16 in, f16 acc.
// OUT_F16: C as f16; else C as bf16 (scores).
// ---------------------------------------------------------------------------
#define BM 128
#define BN 128
#define BK 64
#define STG 3
#define A_ST (BM * BK * 2)            // 16384 B
#define B_ST (BN * BK * 2)            // 16384 B
#define B_BASE (STG * A_ST)           // 49152
#define GSMEM (B_BASE + STG * B_ST)   // 98304 = 96 KB

extern __shared__ __align__(1024) char dyn_smem[];

template <bool OUT_F16>
__global__ __launch_bounds__(256, 2)
void gemm_f16_kernel(const __half* __restrict__ A,
                     const __half* __restrict__ B,
                     void* __restrict__ Cv, int M, int N, int K) {
    const uint32_t sb = smem_u32(dyn_smem);
    const int tid  = threadIdx.x;
    const int wid  = tid >> 5;
    const int lane = tid & 31;
    const int bm = blockIdx.y * BM;
    const int bn = blockIdx.x * BN;
    const int wm = (wid & 1) * 64;    // 2 warps in m
    const int wn = (wid >> 1) * 32;   // 4 warps in n
    const int NK = K / BK;

    uint32_t acc[4][4][2];            // f16x2 accumulators
#pragma unroll
    for (int i = 0; i < 4; i++)
#pragma unroll
        for (int j = 0; j < 4; j++) { acc[i][j][0] = 0u; acc[i][j][1] = 0u; }

    // cp.async staging: rows 128B (64 f16) = 8 x 16B chunks; chunk ^= (row&7)
    auto load_stage = [&](int j) {
        const int s = (j % STG);
        const uint32_t ab = sb + s * A_ST;
        const uint32_t bb = sb + B_BASE + s * B_ST;
        const __half* Aj = A + (size_t)bm * K + (size_t)j * BK;
        const __half* Bj = B + (size_t)bn * K + (size_t)j * BK;
#pragma unroll
        for (int i = 0; i < 4; ++i) {
            int cid = tid + 256 * i;
            int row = cid >> 3, seg = cid & 7;
            uint32_t off = (uint32_t)(row * 128) + (uint32_t)((seg ^ (row & 7)) * 16);
            cp16(ab + off, Aj + (size_t)row * K + seg * 8);
        }
#pragma unroll
        for (int i = 0; i < 4; ++i) {
            int cid = tid + 256 * i;
            int row = cid >> 3, seg = cid & 7;
            uint32_t off = (uint32_t)(row * 128) + (uint32_t)((seg ^ (row & 7)) * 16);
            cp16(bb + off, Bj + (size_t)row * K + seg * 8);
        }
    };

#pragma unroll
    for (int j = 0; j < STG - 1; ++j) { load_stage(j); CP_COMMIT(); }

    // per-thread LDSM address components (validated rounds 8-11)
    const int sub  = lane >> 3;   // 0..3
    const int trow = lane & 7;
    const int a_row_l = wm + (sub & 1) * 8 + trow;   // + mi*16
    const int a_kk    = (sub >> 1) * 8;              // elem col within k-step
    const int b_row_l = wn + (sub >> 1) * 8 + trow;  // + pi*16
    const int b_kk    = (sub & 1) * 8;
    const uint32_t sw = (uint32_t)trow << 4;         // XOR swizzle bytes [6:4]

    for (int kt = 0; kt < NK; ++kt) {
        CP_WAIT(1);
        __syncthreads();
        const int jn = kt + STG - 1;
        if (jn < NK) load_stage(jn);
        CP_COMMIT();

        const int s = kt % STG;
        const uint32_t abase = sb + s * A_ST;
        const uint32_t bbase = sb + B_BASE + s * B_ST;

#pragma unroll
        for (int ks = 0; ks < 4; ++ks) {
            const int k0 = ks * 16;
            uint32_t af[4][4], bf[2][4];
#pragma unroll
            for (int mi = 0; mi < 4; ++mi) {
                uint32_t col = (uint32_t)((k0 + a_kk) * 2) ^ sw;
                ldsm_x4(af[mi], abase + (uint32_t)((a_row_l + mi * 16) * 128) + col);
            }
#pragma unroll
            for (int pi = 0; pi < 2; ++pi) {
                uint32_t col = (uint32_t)((k0 + b_kk) * 2) ^ sw;
                ldsm_x4(bf[pi], bbase + (uint32_t)((b_row_l + pi * 16) * 128) + col);
            }
#pragma unroll
            for (int mi = 0; mi < 4; ++mi)
#pragma unroll
                for (int ni = 0; ni < 4; ++ni)
                    mma16816_f16(acc[mi][ni], af[mi], &bf[ni >> 1][(ni & 1) * 2]);
        }
    }

    // epilogue: acc reg0 = (row, col),(row, col+1); reg1 = (row+8, ...)
    const int g  = lane >> 2;
    const int tg = lane & 3;
    if (OUT_F16) {
        __half* C = (__half*)Cv;
#pragma unroll
        for (int mi = 0; mi < 4; ++mi) {
            const int row = bm + wm + mi * 16 + g;
#pragma unroll
            for (int ni = 0; ni < 4; ++ni) {
                const int col = bn + wn + ni * 8 + tg * 2;
                *(uint32_t*)&C[(size_t)row * N + col]       = acc[mi][ni][0];
                *(uint32_t*)&C[(size_t)(row + 8) * N + col] = acc[mi][ni][1];
            }
        }
    } else {
        __nv_bfloat16* C = (__nv_bfloat16*)Cv;
#pragma unroll
        for (int mi = 0; mi < 4; ++mi) {
            const int row = bm + wm + mi * 16 + g;
#pragma unroll
            for (int ni = 0; ni < 4; ++ni) {
                const int col = bn + wn + ni * 8 + tg * 2;
                float2 f0 = __half22float2(*(__half2*)&acc[mi][ni][0]);
                float2 f1 = __half22float2(*(__half2*)&acc[mi][ni][1]);
                *(__nv_bfloat162*)&C[(size_t)row * N + col] =
                    __floats2bfloat162_rn(f0.x, f0.y);
                *(__nv_bfloat162*)&C[(size_t)(row + 8) * N + col] =
                    __floats2bfloat162_rn(f1.x, f1.y);
            }
        }
    }
}

// ---------------------------------------------------------------------------
// K6: row softmax(scores * inv_d) fused with expmap0+project (bf16 scores in).
// ---------------------------------------------------------------------------
__global__ __launch_bounds__(256)
void softmax_proj_kernel(const __nv_bfloat16* __restrict__ S, float* __restrict__ out,
                         const float* __restrict__ c, int m, float inv_d) {
    __shared__ float sh[16];
    const int row = blockIdx.x;
    const int tid = threadIdx.x;

    const uint4* sv = (const uint4*)(S + (size_t)row * m) + tid * 2;
    uint4 u0 = sv[0], u1 = sv[1];
    float v[16];
    {
        const uint32_t* w = (const uint32_t*)&u0;
#pragma unroll
        for (int i = 0; i < 4; ++i) {
            __nv_bfloat162 h = *(__nv_bfloat162*)&w[i];
            v[2 * i]     = __bfloat162float(h.x);
            v[2 * i + 1] = __bfloat162float(h.y);
        }
        const uint32_t* w2 = (const uint32_t*)&u1;
#pragma unroll
        for (int i = 0; i < 4; ++i) {
            __nv_bfloat162 h = *(__nv_bfloat162*)&w2[i];
            v[8 + 2 * i]     = __bfloat162float(h.x);
            v[8 + 2 * i + 1] = __bfloat162float(h.y);
        }
    }

    float vmax = v[0];
#pragma unroll
    for (int i = 1; i < 16; ++i) vmax = fmaxf(vmax, v[i]);
#pragma unroll
    for (int o = 16; o; o >>= 1) vmax = fmaxf(vmax, __shfl_xor_sync(0xffffffffu, vmax, o));
    if ((tid & 31) == 0) sh[tid >> 5] = vmax;
    __syncthreads();
    const float rmax = fmaxf(fmaxf(fmaxf(sh[0], sh[1]), fmaxf(sh[2], sh[3])),
                             fmaxf(fmaxf(sh[4], sh[5]), fmaxf(sh[6], sh[7])));
    __syncthreads();

    float es = 0.f, e2 = 0.f;
#pragma unroll
    for (int i = 0; i < 16; ++i) {
        float e = __expf((v[i] - rmax) * inv_d);
        v[i] = e;
        es += e;
        e2 = fmaf(e, e, e2);
    }
#pragma unroll
    for (int o = 16; o; o >>= 1) {
        es += __shfl_xor_sync(0xffffffffu, es, o);
        e2 += __shfl_xor_sync(0xffffffffu, e2, o);
    }
    if ((tid & 31) == 0) { sh[tid >> 5] = es; sh[8 + (tid >> 5)] = e2; }
    __syncthreads();
    const float tes = sh[0] + sh[1] + sh[2] + sh[3] + sh[4] + sh[5] + sh[6] + sh[7];
    const float te2 = sh[8] + sh[9] + sh[10] + sh[11] + sh[12] + sh[13] + sh[14] + sh[15];

    const float inv = 1.f / tes;
    const float rn  = fmaxf(sqrtf(te2) * inv, MIN_NORM);
    const float sc  = sqrtf(c[0]);
    const float t   = fminf(tanhf(sc * rn), 1.0f - PROJ_EPS);
    const float scale = (t / (sc * rn)) * inv;

    float4* o = (float4*)(out + (size_t)row * m) + tid * 4;
#pragma unroll
    for (int i = 0; i < 4; ++i)
        o[i] = make_float4(v[4 * i] * scale, v[4 * i + 1] * scale,
                           v[4 * i + 2] * scale, v[4 * i + 3] * scale);
}

// ---------------------------------------------------------------------------
// kernel_launch: inputs: query[n,d], context[m,d], W[d,d], c[1]
// ---------------------------------------------------------------------------
extern "C" void kernel_launch(void* const* d_in, const int* in_sizes, int n_in,
                              void* d_out, int out_size) {
    const float* query   = (const float*)d_in[0];
    const float* context = (const float*)d_in[1];
    const float* W       = (const float*)d_in[2];
    const float* c       = (const float*)d_in[3];

    const int d = (int)(sqrt((double)in_sizes[2]) + 0.5);
    const int n = in_sizes[0] / d;
    const int m = in_sizes[1] / d;

    __half *qs, *cs, *wb, *q2;
    __nv_bfloat16* sco;
    cudaGetSymbolAddress((void**)&qs,  g_qs);
    cudaGetSymbolAddress((void**)&cs,  g_cs);
    cudaGetSymbolAddress((void**)&wb,  g_wb);
    cudaGetSymbolAddress((void**)&q2,  g_q2);
    cudaGetSymbolAddress((void**)&sco, g_scores);

    cudaFuncSetAttribute(gemm_f16_kernel<true>,
                         cudaFuncAttributeMaxDynamicSharedMemorySize, GSMEM);
    cudaFuncSetAttribute(gemm_f16_kernel<false>,
                         cudaFuncAttributeMaxDynamicSharedMemorySize, GSMEM);

    // K1/K2: hyperbolic row scaling -> f16
    scale_rows_kernel<<<n, 256>>>(query, qs, c, d);
    scale_rows_kernel<<<m, 256>>>(context, cs, c, d);

    // K3: W -> f16
    const int n4 = (d * d) / 4;
    convert_w_kernel<<<(n4 + 255) / 256, 256>>>((const float4*)W, (__half2*)wb, n4);

    // K4: q2[n,d] = qs @ wb^T  (f16 out)
    gemm_f16_kernel<true><<<dim3(d / BN, n / BM), 256, GSMEM>>>(qs, wb, (void*)q2, n, d, d);

    // K5: scores[n,m] = q2 @ cs^T  (bf16 out)
    gemm_f16_kernel<false><<<dim3(m / BN, n / BM), 256, GSMEM>>>(q2, cs, (void*)sco, n, m, d);

    // K6: softmax(scores/d) + expmap0/project -> out (fp32)
    softmax_proj_kernel<<<n, 256>>>(sco, (float*)d_out, c, m, 1.0f / (float)d);
}